// round 7
// baseline (speedup 1.0000x reference)
#include <cuda_runtime.h>

#define TLEN    1024
#define BATCH   64
#define NBAND   2
#define NTH     256                 // threads per band block
#define RPT     2                   // rows per thread (NTH*RPT = 512 rows/band)
#define NPAIR   512                 // column pairs (2 cols per step)
#define NSTEP   (NPAIR + NTH - 1)   // 767
#define G       8                   // pairs per handoff group
#define NGROUPS (NPAIR / G)         // 64
#define INFV    1e30f

// Cross-band mailbox. Flags are re-zeroed by init_kernel EVERY launch, so no
// reliance on .bss zero-init and no consumer-side resets.
__device__ float4 g_hand[BATCH][NPAIR];   // row-511 (C,L) at {c0,c1} per pair
__device__ int    g_flag[BATCH][NGROUPS]; // 0 = empty, 1 = group ready
__device__ float  g_losses[BATCH];
__device__ unsigned int g_done;

__global__ void init_kernel() {
    const int i = blockIdx.x * blockDim.x + threadIdx.x;  // 16*256 = 4096
    ((int*)g_flag)[i] = 0;
    if (i == 0) g_done = 0;
}

__device__ __forceinline__ float sqrt_approx(float x) {
    float r; asm("sqrt.approx.f32 %0, %1;" : "=f"(r) : "f"(x)); return r;
}
__device__ __forceinline__ float4 ldcg4(const float4* p) {
    float4 v;
    asm volatile("ld.global.cg.v4.f32 {%0,%1,%2,%3}, [%4];"
                 : "=f"(v.x), "=f"(v.y), "=f"(v.z), "=f"(v.w) : "l"(p));
    return v;
}
__device__ __forceinline__ void stcg4(float4* p, float4 v) {
    asm volatile("st.global.cg.v4.f32 [%0], {%1,%2,%3,%4};"
                 :: "l"(p), "f"(v.x), "f"(v.y), "f"(v.z), "f"(v.w));
}
__device__ __forceinline__ int ld_acq(const int* p) {
    int v; asm volatile("ld.acquire.gpu.global.b32 %0, [%1];" : "=r"(v) : "l"(p));
    return v;
}
__device__ __forceinline__ void st_rel(int* p, int v) {
    asm volatile("st.release.gpu.global.b32 [%0], %1;" :: "l"(p), "r"(v));
}

// DP carried:
//   C[i,j] = D(i,j) + min(diag, up, left)
//   L[i,j] = L1w(i,j) + L[parent], parent = first-min in order (diag, up,
// left) == reference backtrace rule, so loss = L[T-1,T-1] (no backtrace).
// blk = band*64 + b. Band 0 = rows [0,512), band 1 = rows [512,1024).
// Band 0's bottom thread streams row 511 to band 1's thread 0 via g_hand,
// published per 8-pair group with release, consumed with acquire.
__global__ void __launch_bounds__(NTH, 1)
dtw_kernel(const float* __restrict__ preds, const float* __restrict__ targs,
           const float* __restrict__ subcoef, float* __restrict__ out)
{
    __shared__ float4 qs[NPAIR];            // (qx0,qy0,qx1,qy1) per pair
    __shared__ float4 bnd[2][NTH + 1];      // boundary rows, ghost slot 0

    const int blk  = blockIdx.x;
    const int band = blk >> 6;
    const int b    = blk & 63;
    const int t    = threadIdx.x;

    const float* P = preds + (size_t)b * TLEN * 4;
    const float* Q = targs + (size_t)b * TLEN * 4;

    for (int k = t; k < NPAIR; k += NTH) {
        float4 a = *(const float4*)(Q + 8 * k);
        float4 c = *(const float4*)(Q + 8 * k + 4);
        qs[k] = make_float4(a.x, a.y, c.x, c.y);
    }
    float px[RPT], py[RPT];
    const int rb = band * (NTH * RPT) + t * RPT;
#pragma unroll
    for (int r = 0; r < RPT; r++) {
        px[r] = P[(rb + r) * 4 + 0];
        py[r] = P[(rb + r) * 4 + 1];
    }
    const float sc0 = subcoef[0], sc1 = subcoef[1];

    // Feeder prefetch registers: pairs k+1, k+2, k+3 of the handoff row.
    float4 fA = make_float4(0,0,0,0), fB = fA, fC = fA;

    if (t == 0) {
        if (band == 0) {
            float4 inf4 = make_float4(INFV, 0.f, INFV, 0.f);
            bnd[0][0] = inf4; bnd[1][0] = inf4;   // constant top boundary
        } else {
            while (ld_acq(&g_flag[b][0]) == 0) { }   // group 0 (pairs 0..7)
            bnd[1][0] = ldcg4(&g_hand[b][0]);        // pair 0, read at step 0
            fA = ldcg4(&g_hand[b][1]);
            fB = ldcg4(&g_hand[b][2]);
            fC = ldcg4(&g_hand[b][3]);
        }
    }

    float Cl[RPT], Ll[RPT];                  // own rows at col c-1
#pragma unroll
    for (int r = 0; r < RPT; r++) { Cl[r] = INFV; Ll[r] = 0.f; }
    float bCp = INFV, bLp = 0.f;             // neighbor bottom @ c0-1 (diag lag)

    __syncthreads();

    const bool producer = (band == 0) && (t == NTH - 1);
    const bool feeder   = (band == 1) && (t == 0);

    for (int s = 0; s < NSTEP; ++s) {
        const int k  = s - t;
        const int Pw = s & 1;
        if (k >= 0 && k < NPAIR) {
            const float4 bv = bnd[Pw ^ 1][t];     // row above at {c0, c1}
            const float4 q  = qs[k];

            float A[RPT], LA[RPT];                // column c0 = 2k
            {
                float dg = bCp, dgL = bLp, up = bv.x, upL = bv.y;
#pragma unroll
                for (int r = 0; r < RPT; r++) {
                    const float dx = px[r] - q.x, dy = py[r] - q.y;
                    const float D  = sqrt_approx(fmaf(dx, dx, dy * dy));
                    const float m1  = fminf(dg, up);
                    const float m1L = (dg <= up) ? dgL : upL;
                    float m  = fminf(m1, Cl[r]);
                    float Lp = (m1 <= Cl[r]) ? m1L : Ll[r];
                    if (r == 0 && band == 0 && t == 0 && k == 0) { m = 0.f; Lp = 0.f; }
                    A[r]  = D + m;
                    LA[r] = fmaf(fabsf(dy), sc1, fabsf(dx) * sc0) + Lp;
                    dg = Cl[r]; dgL = Ll[r];
                    up = A[r];  upL = LA[r];
                }
            }
            float Bv[RPT], LB[RPT];               // column c1 = 2k+1
            {
                float dg = bv.x, dgL = bv.y, up = bv.z, upL = bv.w;
#pragma unroll
                for (int r = 0; r < RPT; r++) {
                    const float dx = px[r] - q.z, dy = py[r] - q.w;
                    const float D  = sqrt_approx(fmaf(dx, dx, dy * dy));
                    const float m1  = fminf(dg, up);
                    const float m1L = (dg <= up) ? dgL : upL;
                    const float m  = fminf(m1, A[r]);
                    const float Lp = (m1 <= A[r]) ? m1L : LA[r];
                    Bv[r] = D + m;
                    LB[r] = fmaf(fabsf(dy), sc1, fabsf(dx) * sc0) + Lp;
                    dg = A[r];  dgL = LA[r];
                    up = Bv[r]; upL = LB[r];
                }
            }
#pragma unroll
            for (int r = 0; r < RPT; r++) { Cl[r] = Bv[r]; Ll[r] = LB[r]; }
            bCp = bv.z; bLp = bv.w;

            const float4 bot = make_float4(A[RPT-1], LA[RPT-1], Bv[RPT-1], LB[RPT-1]);
            bnd[Pw][t + 1] = bot;

            if (producer) {
                stcg4(&g_hand[b][k], bot);
                if ((k & (G - 1)) == G - 1)       // group complete -> publish
                    st_rel(&g_flag[b][k >> 3], 1);
            }
            if (feeder) {
                if (k + 1 < NPAIR) bnd[Pw][0] = fA;   // pair k+1 top boundary
                fA = fB; fB = fC;
                const int lk = k + 4;
                if (lk < NPAIR) {
                    if ((lk & (G - 1)) == 0) {        // entering a new group
                        const int* fp = &g_flag[b][lk >> 3];
                        while (ld_acq(fp) == 0) { }
                    }
                    fC = ldcg4(&g_hand[b][lk]);
                }
            }
            if (band == 1 && t == NTH - 1 && k == NPAIR - 1)  // cell (1023,1023)
                g_losses[b] = LB[RPT - 1];
        }
        __syncthreads();
    }

    // Last of the 128 blocks sums all batch losses in fixed order.
    if (t == NTH - 1) {
        __threadfence();
        unsigned int old = atomicInc(&g_done, NBAND * BATCH - 1);
        if (old == NBAND * BATCH - 1) {
            __threadfence();
            float sum = 0.f;
#pragma unroll
            for (int i = 0; i < BATCH; i++) sum += __ldcg(&g_losses[i]);
            out[0] = sum;
        }
    }
}

extern "C" void kernel_launch(void* const* d_in, const int* in_sizes, int n_in,
                              void* d_out, int out_size)
{
    const float* preds   = (const float*)d_in[0];
    const float* targs   = (const float*)d_in[1];
    const float* subcoef = (const float*)d_in[2];
    float* out = (float*)d_out;
    (void)in_sizes; (void)n_in; (void)out_size;

    init_kernel<<<16, 256>>>();
    dtw_kernel<<<NBAND * BATCH, NTH>>>(preds, targs, subcoef, out);
}

// round 8
// speedup vs baseline: 1.4308x; 1.4308x over previous
#include <cuda_runtime.h>
#include <cstdint>

#define TLEN    1024
#define BATCH   64
#define NTH     128                 // threads per band CTA
#define RPT     4                   // rows per thread (NTH*RPT = 512 rows/band)
#define NPAIR   512                 // column pairs (2 cols per step)
#define NSTEP   (NPAIR + NTH - 1)   // 639
#define G       8                   // pairs per flag group
#define NGROUPS (NPAIR / G)         // 64
#define INFV    1e30f

__device__ float g_losses[BATCH];
__device__ unsigned int g_done;

__global__ void init_kernel() { g_done = 0; }

__device__ __forceinline__ float sqrt_approx(float x) {
    float r; asm("sqrt.approx.f32 %0, %1;" : "=f"(r) : "f"(x)); return r;
}
__device__ __forceinline__ uint32_t smem_u32(const void* p) {
    uint32_t a;
    asm("{ .reg .u64 tmp; cvta.to.shared.u64 tmp, %1; cvt.u32.u64 %0, tmp; }"
        : "=r"(a) : "l"(p));
    return a;
}
__device__ __forceinline__ uint32_t mapa_rank(uint32_t laddr, uint32_t rank) {
    uint32_t r;
    asm("mapa.shared::cluster.u32 %0, %1, %2;" : "=r"(r) : "r"(laddr), "r"(rank));
    return r;
}
__device__ __forceinline__ void st_dsmem4(uint32_t addr, float4 v) {
    asm volatile("st.shared::cluster.v4.f32 [%0], {%1,%2,%3,%4};"
                 :: "r"(addr), "f"(v.x), "f"(v.y), "f"(v.z), "f"(v.w) : "memory");
}
__device__ __forceinline__ void st_dsmem_i(uint32_t addr, int v) {
    asm volatile("st.shared::cluster.b32 [%0], %1;" :: "r"(addr), "r"(v) : "memory");
}
__device__ __forceinline__ void fence_cluster() {
    asm volatile("fence.acq_rel.cluster;" ::: "memory");
}

// DP carried:
//   C[i,j] = D(i,j) + min(diag, up, left)
//   L[i,j] = L1w(i,j) + L[parent], parent = first-min in order (diag, up,
// left) == reference backtrace rule, so loss = L[T-1,T-1] (no backtrace).
// Cluster of 2 CTAs per batch: rank 0 = rows [0,512), rank 1 = rows
// [512,1024). Rank 0's bottom thread writes its row-511 boundary straight
// into rank 1's smem ring via DSMEM, publishing a flag per 8-pair group.
__global__ void __launch_bounds__(NTH, 1) __cluster_dims__(2, 1, 1)
dtw_kernel(const float* __restrict__ preds, const float* __restrict__ targs,
           const float* __restrict__ subcoef, float* __restrict__ out)
{
    __shared__ float4 qs[NPAIR];          // (qx0,qy0,qx1,qy1) per pair
    __shared__ float4 bnd[2][NTH + 1];    // boundary rows, ghost slot 0
    __shared__ float4 ring[NPAIR];        // consumer: handoff row from peer
    __shared__ int    flags[NGROUPS];     // consumer: group-ready flags

    const int b = blockIdx.x >> 1;
    uint32_t rank; asm("mov.u32 %0, %%cluster_ctarank;" : "=r"(rank));
    const int band = (int)rank;
    const int t = threadIdx.x;

    const float* P = preds + (size_t)b * TLEN * 4;
    const float* Q = targs + (size_t)b * TLEN * 4;

    for (int k = t; k < NPAIR; k += NTH) {
        float4 a = *(const float4*)(Q + 8 * k);
        float4 c = *(const float4*)(Q + 8 * k + 4);
        qs[k] = make_float4(a.x, a.y, c.x, c.y);
    }
    for (int i = t; i < NGROUPS; i += NTH) flags[i] = 0;   // per-launch reset

    float px[RPT], py[RPT];
    const int rb = band * (NTH * RPT) + t * RPT;
#pragma unroll
    for (int r = 0; r < RPT; r++) {
        px[r] = P[(rb + r) * 4 + 0];
        py[r] = P[(rb + r) * 4 + 1];
    }
    const float sc0 = subcoef[0], sc1 = subcoef[1];

    // Producer: peer (rank 1) addresses of ring + flags.
    uint32_t ringPeer = 0, flagPeer = 0;
    if (band == 0 && t == NTH - 1) {
        ringPeer = mapa_rank(smem_u32(&ring[0]), 1);
        flagPeer = mapa_rank(smem_u32(&flags[0]), 1);
    }
    if (band == 0 && t == 0) {
        float4 inf4 = make_float4(INFV, 0.f, INFV, 0.f);
        bnd[0][0] = inf4; bnd[1][0] = inf4;     // constant top boundary
    }

    __syncthreads();
    asm volatile("barrier.cluster.arrive.aligned;" ::: "memory");
    asm volatile("barrier.cluster.wait.aligned;" ::: "memory");

    if (band == 1 && t == 0) {                  // stage pair 0 for step 0
        while (*(volatile int*)&flags[0] == 0) { }
        fence_cluster();
        bnd[1][0] = ring[0];
    }

    float Cl[RPT], Ll[RPT];                     // own rows at col c-1
#pragma unroll
    for (int r = 0; r < RPT; r++) { Cl[r] = INFV; Ll[r] = 0.f; }
    float bCp = INFV, bLp = 0.f;                // neighbor bottom @ c0-1

    __syncthreads();

    const bool producer = (band == 0) && (t == NTH - 1);
    const bool feeder   = (band == 1) && (t == 0);

    for (int s = 0; s < NSTEP; ++s) {
        const int k  = s - t;
        const int Pw = s & 1;
        if (k >= 0 && k < NPAIR) {
            const float4 bv = bnd[Pw ^ 1][t];   // row above at {c0, c1}
            const float4 q  = qs[k];

            float A[RPT], LA[RPT];              // column c0 = 2k
            {
                float dg = bCp, dgL = bLp, up = bv.x, upL = bv.y;
#pragma unroll
                for (int r = 0; r < RPT; r++) {
                    const float dx = px[r] - q.x, dy = py[r] - q.y;
                    const float D  = sqrt_approx(fmaf(dx, dx, dy * dy));
                    const float m1  = fminf(dg, up);
                    const float m1L = (dg <= up) ? dgL : upL;
                    float m  = fminf(m1, Cl[r]);
                    float Lp = (m1 <= Cl[r]) ? m1L : Ll[r];
                    if (r == 0 && band == 0 && t == 0 && k == 0) { m = 0.f; Lp = 0.f; }
                    A[r]  = D + m;
                    LA[r] = fmaf(fabsf(dy), sc1, fabsf(dx) * sc0) + Lp;
                    dg = Cl[r]; dgL = Ll[r];
                    up = A[r];  upL = LA[r];
                }
            }
            float Bv[RPT], LB[RPT];             // column c1 = 2k+1
            {
                float dg = bv.x, dgL = bv.y, up = bv.z, upL = bv.w;
#pragma unroll
                for (int r = 0; r < RPT; r++) {
                    const float dx = px[r] - q.z, dy = py[r] - q.w;
                    const float D  = sqrt_approx(fmaf(dx, dx, dy * dy));
                    const float m1  = fminf(dg, up);
                    const float m1L = (dg <= up) ? dgL : upL;
                    const float m  = fminf(m1, A[r]);
                    const float Lp = (m1 <= A[r]) ? m1L : LA[r];
                    Bv[r] = D + m;
                    LB[r] = fmaf(fabsf(dy), sc1, fabsf(dx) * sc0) + Lp;
                    dg = A[r];  dgL = LA[r];
                    up = Bv[r]; upL = LB[r];
                }
            }
#pragma unroll
            for (int r = 0; r < RPT; r++) { Cl[r] = Bv[r]; Ll[r] = LB[r]; }
            bCp = bv.z; bLp = bv.w;

            const float4 bot = make_float4(A[RPT-1], LA[RPT-1], Bv[RPT-1], LB[RPT-1]);
            bnd[Pw][t + 1] = bot;

            if (producer) {
                st_dsmem4(ringPeer + (uint32_t)k * 16u, bot);
                if ((k & (G - 1)) == G - 1) {   // group complete -> publish
                    fence_cluster();
                    st_dsmem_i(flagPeer + (uint32_t)(k >> 3) * 4u, 1);
                }
            }
            if (feeder) {
                const int nk = k + 1;
                if (nk < NPAIR) {
                    if ((nk & (G - 1)) == 0) {  // entering a new group
                        while (*(volatile int*)&flags[nk >> 3] == 0) { }
                        fence_cluster();
                    }
                    bnd[Pw][0] = ring[nk];
                }
            }
            if (band == 1 && t == NTH - 1 && k == NPAIR - 1)  // cell (1023,1023)
                g_losses[b] = LB[RPT - 1];
        }
        __syncthreads();
    }

    // Last of the 128 CTAs sums all batch losses in fixed order.
    if (t == NTH - 1) {
        __threadfence();
        unsigned int old = atomicInc(&g_done, 2 * BATCH - 1);
        if (old == 2 * BATCH - 1) {
            __threadfence();
            float sum = 0.f;
#pragma unroll
            for (int i = 0; i < BATCH; i++) sum += __ldcg(&g_losses[i]);
            out[0] = sum;
        }
    }
}

extern "C" void kernel_launch(void* const* d_in, const int* in_sizes, int n_in,
                              void* d_out, int out_size)
{
    const float* preds   = (const float*)d_in[0];
    const float* targs   = (const float*)d_in[1];
    const float* subcoef = (const float*)d_in[2];
    float* out = (float*)d_out;
    (void)in_sizes; (void)n_in; (void)out_size;

    init_kernel<<<1, 1>>>();
    dtw_kernel<<<2 * BATCH, NTH>>>(preds, targs, subcoef, out);
}